// round 17
// baseline (speedup 1.0000x reference)
#include <cuda_runtime.h>
#include <cstdint>

// CTC greedy decode:
//   best[b,t]  = argmax_c probs[b,t,c]           (first max on ties, like jnp.argmax)
//   valid[b,t] = best!=prev_best && best!=blank  (blank = C-1, prev at t=0 is -1)
//   left-pack table[best] for valid positions; pad rest with default_char.
//
// Output is FLOAT32 (harness __output__ dtype): char codes value-cast to float.
// Shapes fixed by the problem: B=1024, T=512, C=128.
//
// R17 change vs R16 (45.8us, DRAM 75.8%, alu 42.3%): move the lane-local 4-way
// max from integer-key domain (4x fkey = 8 ALU ops) to float domain
// (3x FMNMX on the idle fma pipe) and compute the integer monotone key ONCE
// per lane for redux.sync. Tie-break compares floats (FSETP, fma pipe).
// Unroll 4 -> 8 for deeper load MLP. Expect alu% ~30, DRAM% ~84, ~41us.

namespace {
constexpr int T = 512;
constexpr int C = 128;
constexpr int BLANK = C - 1;
constexpr int THREADS = 256;
constexpr int WARPS = THREADS / 32;   // 8

// Monotone map: float bits -> uint with same ordering (sign handled).
// 2 SASS ops: SHF.HI + LOP3 (mask = (u>>31 arith) | 0x80000000; key = u ^ mask).
__device__ __forceinline__ unsigned int fkey(float f) {
    unsigned int u = __float_as_uint(f);
    return u ^ (((unsigned int)((int)u >> 31)) | 0x80000000u);
}

__global__ void __launch_bounds__(THREADS)
ctc_decode_kernel(const float* __restrict__ probs,
                  const int*   __restrict__ table,
                  const int*   __restrict__ dflt_ptr,
                  float*       __restrict__ out)
{
    const int b    = blockIdx.x;
    const int tid  = threadIdx.x;
    const int wid  = tid >> 5;
    const int lane = tid & 31;

    __shared__ short   s_best[T];
    __shared__ float   s_out[T];
    __shared__ float   s_tab[C];
    __shared__ int     s_wsum[WARPS];
    __shared__ float   s_dc;

    if (tid < C) s_tab[tid] = (float)table[tid];
    if (tid == 0) s_dc = (float)(dflt_ptr ? dflt_ptr[0] : 32);

    // ---- Phase 1: per-t argmax. One warp per t; lane loads float4 (coalesced 512B). ----
    const float4* row = reinterpret_cast<const float4*>(probs + (size_t)b * T * C);
    #pragma unroll 8
    for (int t = wid; t < T; t += WARPS) {
        float4 v = row[t * (C / 4) + lane];

        // lane-local max in FLOAT domain (FMNMX -> fma pipe, which is idle)
        const float lmf = fmaxf(fmaxf(v.x, v.y), fmaxf(v.z, v.w));
        // ONE integer monotone key per lane (2 ALU ops)
        const unsigned int lm = fkey(lmf);

        // warp max in one instruction
        const unsigned int wm = __reduce_max_sync(0xFFFFFFFFu, lm);

        // first-index tie-break: lowest lane holding wm, then first of its 4
        // (float equality; keys are injective on floats so lm==wm <=> lmf is
        //  the warp max value).
        const unsigned int hit = __ballot_sync(0xFFFFFFFFu, lm == wm);
        const int wl = __ffs(hit) - 1;
        const int li = (v.x == lmf) ? 0 : (v.y == lmf) ? 1 : (v.z == lmf) ? 2 : 3;
        const int idx = __shfl_sync(0xFFFFFFFFu, lane * 4 + li, wl);

        if (lane == 0) s_best[t] = (short)idx;
    }
    __syncthreads();

    // ---- Phase 2: valid flags + block exclusive scan (2 t-positions per thread). ----
    const float dc = s_dc;
    // pre-fill staging row with default_char (separated from the Phase-3 scatter
    // by the scan's two barriers below, so no race)
    s_out[tid]           = dc;
    s_out[tid + THREADS] = dc;

    const int t0 = 2 * tid, t1 = 2 * tid + 1;
    const int b0 = s_best[t0];
    const int b1 = s_best[t1];
    const int p0 = (t0 == 0) ? -1 : s_best[t0 - 1];
    const int v0 = (b0 != p0) && (b0 != BLANK);
    const int v1 = (b1 != b0) && (b1 != BLANK);
    const int s  = v0 + v1;

    int incl = s;
    #pragma unroll
    for (int off = 1; off < 32; off <<= 1) {
        int n = __shfl_up_sync(0xFFFFFFFFu, incl, off);
        if (lane >= off) incl += n;
    }
    if (lane == 31) s_wsum[wid] = incl;
    __syncthreads();
    if (tid == 0) {
        int acc = 0;
        #pragma unroll
        for (int w = 0; w < WARPS; w++) { int v = s_wsum[w]; s_wsum[w] = acc; acc += v; }
    }
    __syncthreads();

    const int excl = s_wsum[wid] + (incl - s);

    // ---- Phase 3: scatter into staging row, then coalesced store. ----
    if (v0) s_out[excl]      = s_tab[b0];
    if (v1) s_out[excl + v0] = s_tab[b1];
    __syncthreads();

    float* orow = out + (size_t)b * T;
    orow[tid]           = s_out[tid];
    orow[tid + THREADS] = s_out[tid + THREADS];
}
} // namespace

extern "C" void kernel_launch(void* const* d_in, const int* in_sizes, int n_in,
                              void* d_out, int out_size)
{
    // Classify inputs by SIZE, not position:
    //   probs        : the unique largest buffer (B*T*C elements)
    //   default_char : size-1 buffer (may be absent -> fallback 32)
    //   table        : the remaining buffer (C = 128 elements)
    int big_i = 0;
    long long big_sz = -1;
    for (int i = 0; i < n_in; i++) {
        if ((long long)in_sizes[i] > big_sz) { big_sz = in_sizes[i]; big_i = i; }
    }
    const float* probs = (const float*)d_in[big_i];
    const int*   table = nullptr;
    const int*   dflt  = nullptr;
    for (int i = 0; i < n_in; i++) {
        if (i == big_i) continue;
        if (in_sizes[i] == 1) dflt = (const int*)d_in[i];
        else                  table = (const int*)d_in[i];
    }

    float* out = (float*)d_out;
    const int B = out_size / T;   // 1024 for this problem
    ctc_decode_kernel<<<B, THREADS>>>(probs, table, dflt, out);
}